// round 9
// baseline (speedup 1.0000x reference)
#include <cuda_runtime.h>

// Fixed shapes
#define BB 64
#define LL 512
#define HH 768
#define WW 255
#define H4 (HH / 4)      // 192 float4 per H row
#define WPAD 256         // padded words per batch
#define WPB 4            // words per chunk
#define NCHUNK 64        // WPAD/WPB; chunk c==NCHUNK -> cls copy
#define CPB (NCHUNK + 1) // 65 chunks per batch (incl cls)
#define TOTAL (CPB * BB) // 4160 work items
#define GRID 1040        // TOTAL/4: every block does EXACTLY 4 items
#define ITERS 4

// Packed metadata: start | (len<<16), padded to 256/batch (int4-aligned).
__device__ int g_meta[BB * WPAD];

// Kernel A: warp-per-batch scan -> packed (start,len).
__global__ void wordrep_scan_kernel(const int* __restrict__ wl) {
    const int warp = (blockIdx.x * blockDim.x + threadIdx.x) >> 5;
    const int lane = threadIdx.x & 31;
    if (warp >= BB) return;
    const int* wlb = wl + warp * WW;

    int v[8], p = 0;
    #pragma unroll
    for (int i = 0; i < 8; i++) {
        const int idx = lane * 8 + i;
        v[i] = (idx < WW) ? wlb[idx] : 0;
    }
    int pre[8];
    #pragma unroll
    for (int i = 0; i < 8; i++) { pre[i] = p; p += v[i]; }

    int excl = p;
    #pragma unroll
    for (int o = 1; o < 32; o <<= 1) {
        int n = __shfl_up_sync(0xffffffffu, excl, o);
        if (lane >= o) excl += n;
    }
    excl -= p;

    int m[8];
    #pragma unroll
    for (int i = 0; i < 8; i++)
        m[i] = ((1 + excl + pre[i]) & 0xffff) | (v[i] << 16);

    int4* dst = (int4*)&g_meta[warp * WPAD + lane * 8];
    dst[0] = make_int4(m[0], m[1], m[2], m[3]);
    dst[1] = make_int4(m[4], m[5], m[6], m[7]);
}

// Kernel B: persistent gather/mean-pool; 4 items/block, pipelined meta,
// write-through stores (no L2 allocation on the output stream).
__global__ __launch_bounds__(192, 8) void wordrep_gather_kernel(
        const float4* __restrict__ seq,
        float4*       __restrict__ out)
{
    const int t = threadIdx.x;             // float4 column 0..191
    const size_t ctx = (size_t)BB * H4;

    // Prefetch metadata for first item.
    int i0 = blockIdx.x;
    int b0 = i0 / CPB, c0 = i0 - b0 * CPB;
    int4 m = (c0 < NCHUNK) ? *(const int4*)(&g_meta[b0 * WPAD + c0 * WPB])
                           : make_int4(0, 0, 0, 0);

    #pragma unroll
    for (int it = 0; it < ITERS; it++) {
        const int i = blockIdx.x + it * GRID;
        const int b = i / CPB;
        const int c = i - b * CPB;

        // Prefetch NEXT item's metadata (overlaps this item's work).
        int4 mn = make_int4(0, 0, 0, 0);
        if (it + 1 < ITERS) {
            const int in = i + GRID;
            const int bn = in / CPB, cn = in - bn * CPB;
            if (cn < NCHUNK)
                mn = *(const int4*)(&g_meta[bn * WPAD + cn * WPB]);
        }

        if (c == NCHUNK) {
            __stwt(&out[(size_t)b * H4 + t], seq[(size_t)b * LL * H4 + t]);
            m = mn;
            continue;
        }

        int st[WPB], len[WPB];
        st[0] = m.x & 0xffff; len[0] = m.x >> 16;
        st[1] = m.y & 0xffff; len[1] = m.y >> 16;
        st[2] = m.z & 0xffff; len[2] = m.z >> 16;
        st[3] = m.w & 0xffff; len[3] = m.w >> 16;

        const float4* rowb = seq + (size_t)b * LL * H4 + t;

        float4 a[WPB], a2[WPB];
        #pragma unroll
        for (int w = 0; w < WPB; w++)
            a[w] = __ldg(rowb + st[w] * H4);
        #pragma unroll
        for (int w = 0; w < WPB; w++)
            if (len[w] > 1)
                a2[w] = __ldg(rowb + (st[w] + 1) * H4);

        float4* o = out + ctx + ((size_t)b * WW + c * WPB) * H4 + t;
        #pragma unroll
        for (int w = 0; w < WPB; w++) {
            const int gw = c * WPB + w;
            if (gw >= WW) continue;                       // pad word
            float4 r;
            if (len[w] > 0) {
                r = a[w];
                if (len[w] > 1) {
                    r.x += a2[w].x; r.y += a2[w].y;
                    r.z += a2[w].z; r.w += a2[w].w;
                }
                const float inv = 1.0f / (float)len[w];   // exact for 1,2
                r.x *= inv; r.y *= inv; r.z *= inv; r.w *= inv;
            } else {
                r = make_float4(0.f, 0.f, 0.f, 0.f);
            }
            __stwt(&o[(size_t)w * H4], r);                // write-through: keep L2 for input
        }

        m = mn;
    }
}

extern "C" void kernel_launch(void* const* d_in, const int* in_sizes, int n_in,
                              void* d_out, int out_size) {
    (void)in_sizes; (void)n_in; (void)out_size;
    const float4* seq = (const float4*)d_in[0];
    const int*    wl  = (const int*)d_in[1];
    float4*       out = (float4*)d_out;

    wordrep_scan_kernel<<<8, 256>>>(wl);
    wordrep_gather_kernel<<<GRID, 192>>>(seq, out);
}

// round 10
// speedup vs baseline: 1.2020x; 1.2020x over previous
#include <cuda_runtime.h>

// Fixed shapes
#define BB 64
#define LL 512
#define HH 768
#define WW 255
#define H4 (HH / 4)      // 192 float4 per H row
#define WPAD 256         // padded words per batch
#define WPB 4            // words per chunk
#define NCHUNK 64        // WPAD/WPB; chunk c==NCHUNK -> cls copy
#define CPB (NCHUNK + 1) // 65 chunks per batch (incl cls)
#define TOTAL (CPB * BB) // 4160 work items
#define GRID 1040        // TOTAL/4: every block does EXACTLY 4 items
#define ITERS 4

// Packed metadata: start | (len<<16), padded to 256/batch (int4-aligned).
__device__ int g_meta[BB * WPAD];

// Kernel A: warp-per-batch scan -> packed (start,len).
__global__ void wordrep_scan_kernel(const int* __restrict__ wl) {
    const int warp = (blockIdx.x * blockDim.x + threadIdx.x) >> 5;
    const int lane = threadIdx.x & 31;
    if (warp < BB) {
        const int* wlb = wl + warp * WW;

        int v[8], p = 0;
        #pragma unroll
        for (int i = 0; i < 8; i++) {
            const int idx = lane * 8 + i;
            v[i] = (idx < WW) ? wlb[idx] : 0;
        }
        int pre[8];
        #pragma unroll
        for (int i = 0; i < 8; i++) { pre[i] = p; p += v[i]; }

        int excl = p;
        #pragma unroll
        for (int o = 1; o < 32; o <<= 1) {
            int n = __shfl_up_sync(0xffffffffu, excl, o);
            if (lane >= o) excl += n;
        }
        excl -= p;

        int m[8];
        #pragma unroll
        for (int i = 0; i < 8; i++)
            m[i] = ((1 + excl + pre[i]) & 0xffff) | (v[i] << 16);

        int4* dst = (int4*)&g_meta[warp * WPAD + lane * 8];
        dst[0] = make_int4(m[0], m[1], m[2], m[3]);
        dst[1] = make_int4(m[4], m[5], m[6], m[7]);
    }
}

// Kernel B: persistent gather/mean-pool; 4 items/block, pipelined meta.
// Launched with PDL: overlaps its launch/prologue with the scan kernel.
__global__ __launch_bounds__(192, 8) void wordrep_gather_kernel(
        const float4* __restrict__ seq,
        float4*       __restrict__ out)
{
    const int t = threadIdx.x;             // float4 column 0..191
    const size_t ctx = (size_t)BB * H4;

    // Meta-independent prologue (runs concurrently with the scan kernel).
    const int i0 = blockIdx.x;
    const int b0 = i0 / CPB, c0 = i0 - b0 * CPB;

    // Wait for the scan kernel's g_meta writes to be visible.
    cudaGridDependencySynchronize();

    int4 m = (c0 < NCHUNK) ? *(const int4*)(&g_meta[b0 * WPAD + c0 * WPB])
                           : make_int4(0, 0, 0, 0);

    #pragma unroll
    for (int it = 0; it < ITERS; it++) {
        const int i = blockIdx.x + it * GRID;
        const int b = i / CPB;
        const int c = i - b * CPB;

        // Prefetch NEXT item's metadata (overlaps this item's work).
        int4 mn = make_int4(0, 0, 0, 0);
        if (it + 1 < ITERS) {
            const int in = i + GRID;
            const int bn = in / CPB, cn = in - bn * CPB;
            if (cn < NCHUNK)
                mn = *(const int4*)(&g_meta[bn * WPAD + cn * WPB]);
        }

        if (c == NCHUNK) {
            __stcs(&out[(size_t)b * H4 + t], seq[(size_t)b * LL * H4 + t]);
            m = mn;
            continue;
        }

        int st[WPB], len[WPB];
        st[0] = m.x & 0xffff; len[0] = m.x >> 16;
        st[1] = m.y & 0xffff; len[1] = m.y >> 16;
        st[2] = m.z & 0xffff; len[2] = m.z >> 16;
        st[3] = m.w & 0xffff; len[3] = m.w >> 16;

        const float4* rowb = seq + (size_t)b * LL * H4 + t;

        float4 a[WPB], a2[WPB];
        #pragma unroll
        for (int w = 0; w < WPB; w++)
            a[w] = __ldg(rowb + st[w] * H4);
        #pragma unroll
        for (int w = 0; w < WPB; w++)
            if (len[w] > 1)
                a2[w] = __ldg(rowb + (st[w] + 1) * H4);

        float4* o = out + ctx + ((size_t)b * WW + c * WPB) * H4 + t;
        #pragma unroll
        for (int w = 0; w < WPB; w++) {
            const int gw = c * WPB + w;
            if (gw >= WW) continue;                       // pad word
            float4 r;
            if (len[w] > 0) {
                r = a[w];
                if (len[w] > 1) {
                    r.x += a2[w].x; r.y += a2[w].y;
                    r.z += a2[w].z; r.w += a2[w].w;
                }
                const float inv = 1.0f / (float)len[w];   // exact for 1,2
                r.x *= inv; r.y *= inv; r.z *= inv; r.w *= inv;
            } else {
                r = make_float4(0.f, 0.f, 0.f, 0.f);
            }
            __stcs(&o[(size_t)w * H4], r);                // evict-first output
        }

        m = mn;
    }
}

extern "C" void kernel_launch(void* const* d_in, const int* in_sizes, int n_in,
                              void* d_out, int out_size) {
    (void)in_sizes; (void)n_in; (void)out_size;
    const float4* seq = (const float4*)d_in[0];
    const int*    wl  = (const int*)d_in[1];
    float4*       out = (float4*)d_out;

    wordrep_scan_kernel<<<8, 256>>>(wl);

    // Gather with programmatic dependent launch: overlap with the scan.
    cudaLaunchConfig_t cfg = {};
    cfg.gridDim  = dim3(GRID, 1, 1);
    cfg.blockDim = dim3(192, 1, 1);
    cfg.dynamicSmemBytes = 0;
    cfg.stream = 0;
    cudaLaunchAttribute attr[1];
    attr[0].id = cudaLaunchAttributeProgrammaticStreamSerialization;
    attr[0].val.programmaticStreamSerializationAllowed = 1;
    cfg.attrs = attr;
    cfg.numAttrs = 1;
    cudaLaunchKernelEx(&cfg, wordrep_gather_kernel, seq, out);
}

// round 11
// speedup vs baseline: 1.3662x; 1.1366x over previous
#include <cuda_runtime.h>

// Fixed shapes
#define BB 64
#define LL 512
#define HH 768
#define WW 255
#define H4 (HH / 4)        // 192 float4 per H row
#define WPBLK 16           // words per block
#define BLKPB 16           // blocks per batch (16*16=256 >= 255)
#define GRID (BB * BLKPB)  // 1024 blocks, single wave

// One fused kernel: per-block scan (amortized over 16 words) + gather/mean-pool.
__global__ __launch_bounds__(192, 8) void wordrep_fused_kernel(
        const float4* __restrict__ seq,   // (B, L, H) as float4
        const int*    __restrict__ wl,    // (B, W)
        float4*       __restrict__ out)   // [cls B*H4][ctx B*W*H4]
{
    const int blk  = blockIdx.x;
    const int b    = blk >> 4;            // batch
    const int j    = blk & 15;            // word-group within batch
    const int t    = threadIdx.x;         // float4 column 0..191
    const int lane = t & 31;
    const int w0   = j * WPBLK;           // first word of this block

    const int* wlb = wl + b * WW;

    __shared__ int s_part[6];
    __shared__ __align__(16) int s_meta[WPBLK];   // start | (len<<16)

    // ---- prefix base = 1 + sum(wl[b, 0..w0)) ; w0 <= 240 ----
    int psum = 0;
    #pragma unroll
    for (int i = t; i < w0; i += 192) psum += wlb[i];   // <= 2 loads/thread
    #pragma unroll
    for (int o = 16; o > 0; o >>= 1)
        psum += __shfl_down_sync(0xffffffffu, psum, o);
    if (lane == 0) s_part[t >> 5] = psum;
    __syncthreads();

    // ---- warp 0: 16-word exclusive scan -> packed meta in smem ----
    if (t < 32) {
        int base = 1;
        #pragma unroll
        for (int k = 0; k < 6; k++) base += s_part[k];
        const int wi  = w0 + t;
        const int len = (t < WPBLK && wi < WW) ? wlb[wi] : 0;
        int ex = len;
        #pragma unroll
        for (int o = 1; o < 16; o <<= 1) {
            int n = __shfl_up_sync(0xffffffffu, ex, o);
            if (lane >= o) ex += n;
        }
        ex -= len;                                    // exclusive
        if (t < WPBLK)
            s_meta[t] = ((base + ex) & 0xffff) | (len << 16);
    }
    __syncthreads();

    // ---- gather/mean-pool 4 chunks of 4 words ----
    const float4* rowb = seq + (size_t)b * LL * H4 + t;
    float4* obase = out + (size_t)BB * H4 + ((size_t)b * WW + w0) * H4 + t;

    #pragma unroll
    for (int cc = 0; cc < 4; cc++) {
        const int4 m = *(const int4*)&s_meta[cc * 4];
        int st[4], len[4];
        st[0] = m.x & 0xffff; len[0] = m.x >> 16;
        st[1] = m.y & 0xffff; len[1] = m.y >> 16;
        st[2] = m.z & 0xffff; len[2] = m.z >> 16;
        st[3] = m.w & 0xffff; len[3] = m.w >> 16;

        float4 a[4], a2[4];
        #pragma unroll
        for (int w = 0; w < 4; w++)
            a[w] = __ldg(rowb + st[w] * H4);
        #pragma unroll
        for (int w = 0; w < 4; w++)
            if (len[w] > 1)
                a2[w] = __ldg(rowb + (st[w] + 1) * H4);

        #pragma unroll
        for (int w = 0; w < 4; w++) {
            const int gw = w0 + cc * 4 + w;
            if (gw >= WW) continue;                   // pad word (only gw==255)
            float4 r;
            if (len[w] > 0) {
                r = a[w];
                if (len[w] > 1) {
                    r.x += a2[w].x; r.y += a2[w].y;
                    r.z += a2[w].z; r.w += a2[w].w;
                }
                const float inv = 1.0f / (float)len[w];   // exact for 1,2
                r.x *= inv; r.y *= inv; r.z *= inv; r.w *= inv;
            } else {
                r = make_float4(0.f, 0.f, 0.f, 0.f);
            }
            __stcs(&obase[((size_t)(cc * 4 + w)) * H4], r);
        }
    }

    // ---- cls row: block 15 of each batch ----
    if (j == BLKPB - 1)
        __stcs(&out[(size_t)b * H4 + t], __ldg(&seq[(size_t)b * LL * H4 + t]));
}

extern "C" void kernel_launch(void* const* d_in, const int* in_sizes, int n_in,
                              void* d_out, int out_size) {
    (void)in_sizes; (void)n_in; (void)out_size;
    const float4* seq = (const float4*)d_in[0];
    const int*    wl  = (const int*)d_in[1];
    float4*       out = (float4*)d_out;

    wordrep_fused_kernel<<<GRID, 192>>>(seq, wl, out);
}